// round 1
// baseline (speedup 1.0000x reference)
#include <cuda_runtime.h>
#include <math.h>

#define S_LEN  2048
#define E_DIM  1024
#define H_NUM  16
#define D_HEAD 64
#define B_NUM  2
#define M_TOT  (B_NUM * S_LEN)   // 4096 rows

// Scratch for Q, K, V projections (16 MB each)
__device__ float g_Q[(size_t)M_TOT * E_DIM];
__device__ float g_K[(size_t)M_TOT * E_DIM];
__device__ float g_V[(size_t)M_TOT * E_DIM];

// ---------------------------------------------------------------------------
// Kernel 1: C = x @ W^T for W in {Wq, Wk, Wv} (blockIdx.z selects which).
// x: [4096, 1024], W: [1024, 1024] row-major [n][k].
// 128x128 tile, BK=16, 256 threads, 8x8 per thread (strided mapping).
// ---------------------------------------------------------------------------
__global__ __launch_bounds__(256) void qkv_gemm(
    const float* __restrict__ x,
    const float* __restrict__ Wq,
    const float* __restrict__ Wk,
    const float* __restrict__ Wv)
{
    __shared__ float As[16 * 132];
    __shared__ float Bs[16 * 132];

    const float* W;
    float* C;
    if (blockIdx.z == 0)      { W = Wq; C = g_Q; }
    else if (blockIdx.z == 1) { W = Wk; C = g_K; }
    else                      { W = Wv; C = g_V; }

    const int m0 = blockIdx.y * 128;
    const int n0 = blockIdx.x * 128;
    const int t  = threadIdx.x;
    const int ty = t >> 4;       // 0..15
    const int tx = t & 15;       // 0..15

    float acc[8][8];
#pragma unroll
    for (int i = 0; i < 8; i++)
#pragma unroll
        for (int j = 0; j < 8; j++) acc[i][j] = 0.0f;

    for (int k0 = 0; k0 < E_DIM; k0 += 16) {
#pragma unroll
        for (int i = 0; i < 2; i++) {
            int s   = t + i * 256;     // 0..511 float4 slots
            int row = s >> 2;          // 0..127
            int kc  = s & 3;           // 0..3 (float4 chunk of K)
            float4 av = *(const float4*)&x[(size_t)(m0 + row) * E_DIM + k0 + kc * 4];
            float4 bv = *(const float4*)&W[(size_t)(n0 + row) * E_DIM + k0 + kc * 4];
            As[(kc * 4 + 0) * 132 + row] = av.x;
            As[(kc * 4 + 1) * 132 + row] = av.y;
            As[(kc * 4 + 2) * 132 + row] = av.z;
            As[(kc * 4 + 3) * 132 + row] = av.w;
            Bs[(kc * 4 + 0) * 132 + row] = bv.x;
            Bs[(kc * 4 + 1) * 132 + row] = bv.y;
            Bs[(kc * 4 + 2) * 132 + row] = bv.z;
            Bs[(kc * 4 + 3) * 132 + row] = bv.w;
        }
        __syncthreads();

#pragma unroll
        for (int kk = 0; kk < 16; kk++) {
            float a[8], b[8];
#pragma unroll
            for (int i = 0; i < 8; i++) a[i] = As[kk * 132 + ty + 16 * i];
#pragma unroll
            for (int j = 0; j < 8; j++) b[j] = Bs[kk * 132 + tx + 16 * j];
#pragma unroll
            for (int i = 0; i < 8; i++)
#pragma unroll
                for (int j = 0; j < 8; j++)
                    acc[i][j] = fmaf(a[i], b[j], acc[i][j]);
        }
        __syncthreads();
    }

#pragma unroll
    for (int i = 0; i < 8; i++) {
        int m = m0 + ty + 16 * i;
#pragma unroll
        for (int j = 0; j < 8; j++)
            C[(size_t)m * E_DIM + n0 + tx + 16 * j] = acc[i][j];
    }
}

// ---------------------------------------------------------------------------
// Kernel 2: L2-normalize each head chunk (64 contiguous floats) of Q and K.
// Folds g_scale into Q (scores = (g*q_hat) . k_hat). One warp per chunk.
// grid.y: 0 -> Q (scale g), 1 -> K (scale 1).
// ---------------------------------------------------------------------------
__global__ __launch_bounds__(256) void norm_heads(const float* __restrict__ gptr)
{
    int warp = (blockIdx.x * blockDim.x + threadIdx.x) >> 5;
    int lane = threadIdx.x & 31;
    const int total = M_TOT * H_NUM;  // 65536 chunks of 64
    if (warp >= total) return;

    float* buf = (blockIdx.y == 0) ? g_Q : g_K;
    float  sc  = (blockIdx.y == 0) ? *gptr : 1.0f;
    float* p   = buf + (size_t)warp * 64;

    float2 v = *(float2*)&p[lane * 2];
    float ss = v.x * v.x + v.y * v.y;
#pragma unroll
    for (int m = 16; m > 0; m >>= 1) ss += __shfl_xor_sync(0xffffffffu, ss, m);
    float inv = sc / fmaxf(sqrtf(ss), 1e-12f);
    v.x *= inv; v.y *= inv;
    *(float2*)&p[lane * 2] = v;
}

// ---------------------------------------------------------------------------
// Kernel 3: flash attention, fp32. Br=Bc=64. 256 threads, 4x4 microtile.
// grid = (S/64, H, B). Dynamic smem: Qs(64x64) Ks(64x65) Vs(64x64) Ps(64x64).
// ---------------------------------------------------------------------------
__global__ __launch_bounds__(256) void attn_kernel(float* __restrict__ out)
{
    extern __shared__ float sm[];
    float* Qs = sm;                 // 64*64
    float* Ks = Qs + 64 * 64;       // 64*65 (padded: conflict-free col reads)
    float* Vs = Ks + 64 * 65;       // 64*64
    float* Ps = Vs + 64 * 64;       // 64*64

    const int b  = blockIdx.z;
    const int h  = blockIdx.y;
    const int q0 = blockIdx.x * 64;
    const int t  = threadIdx.x;
    const int ty = t >> 4;   // 0..15
    const int tx = t & 15;   // 0..15

    const float* Qg = g_Q + (size_t)b * S_LEN * E_DIM + h * D_HEAD;
    const float* Kg = g_K + (size_t)b * S_LEN * E_DIM + h * D_HEAD;
    const float* Vg = g_V + (size_t)b * S_LEN * E_DIM + h * D_HEAD;

    // Load Q tile [64 x 64]
#pragma unroll
    for (int i = 0; i < 4; i++) {
        int s  = t + i * 256;      // 0..1023 float4 slots
        int r  = s >> 4;           // 0..63
        int c4 = s & 15;           // 0..15
        float4 v = *(const float4*)&Qg[(size_t)(q0 + r) * E_DIM + c4 * 4];
        *(float4*)&Qs[r * 64 + c4 * 4] = v;
    }

    float m_i[4], l_i[4], o[4][4];
#pragma unroll
    for (int i = 0; i < 4; i++) {
        m_i[i] = -INFINITY; l_i[i] = 0.0f;
#pragma unroll
        for (int j = 0; j < 4; j++) o[i][j] = 0.0f;
    }

    for (int kt = 0; kt < S_LEN / 64; kt++) {
        __syncthreads();   // prev iter done reading Ks/Vs/Ps (and Q store done)
        // Load K tile (stride 65, scalar stores) + V tile (stride 64, vec)
#pragma unroll
        for (int i = 0; i < 4; i++) {
            int s  = t + i * 256;
            int r  = s >> 4;
            int c4 = s & 15;
            float4 kv = *(const float4*)&Kg[(size_t)(kt * 64 + r) * E_DIM + c4 * 4];
            Ks[r * 65 + c4 * 4 + 0] = kv.x;
            Ks[r * 65 + c4 * 4 + 1] = kv.y;
            Ks[r * 65 + c4 * 4 + 2] = kv.z;
            Ks[r * 65 + c4 * 4 + 3] = kv.w;
            float4 vv = *(const float4*)&Vg[(size_t)(kt * 64 + r) * E_DIM + c4 * 4];
            *(float4*)&Vs[r * 64 + c4 * 4] = vv;
        }
        __syncthreads();

        // Scores: s[i][j] = sum_d Q[ty+16i][d] * K[tx+16j][d]  (g folded into Q)
        float sv[4][4];
#pragma unroll
        for (int i = 0; i < 4; i++)
#pragma unroll
            for (int j = 0; j < 4; j++) sv[i][j] = 0.0f;

#pragma unroll 4
        for (int d = 0; d < 64; d++) {
            float a[4], bb[4];
#pragma unroll
            for (int i = 0; i < 4; i++) a[i]  = Qs[(ty + 16 * i) * 64 + d];
#pragma unroll
            for (int j = 0; j < 4; j++) bb[j] = Ks[(tx + 16 * j) * 65 + d];
#pragma unroll
            for (int i = 0; i < 4; i++)
#pragma unroll
                for (int j = 0; j < 4; j++)
                    sv[i][j] = fmaf(a[i], bb[j], sv[i][j]);
        }

        // Online softmax per row (row group = 16 lanes sharing ty)
#pragma unroll
        for (int i = 0; i < 4; i++) {
            float rm = sv[i][0];
#pragma unroll
            for (int j = 1; j < 4; j++) rm = fmaxf(rm, sv[i][j]);
#pragma unroll
            for (int x = 1; x < 16; x <<= 1)
                rm = fmaxf(rm, __shfl_xor_sync(0xffffffffu, rm, x, 16));
            float mn   = fmaxf(m_i[i], rm);
            float corr = __expf(m_i[i] - mn);
            m_i[i] = mn;
            float rs = 0.0f;
#pragma unroll
            for (int j = 0; j < 4; j++) {
                sv[i][j] = __expf(sv[i][j] - mn);
                rs += sv[i][j];
            }
#pragma unroll
            for (int x = 1; x < 16; x <<= 1)
                rs += __shfl_xor_sync(0xffffffffu, rs, x, 16);
            l_i[i] = l_i[i] * corr + rs;
#pragma unroll
            for (int j = 0; j < 4; j++) o[i][j] *= corr;
#pragma unroll
            for (int j = 0; j < 4; j++)
                Ps[(ty + 16 * i) * 64 + tx + 16 * j] = sv[i][j];
        }
        __syncthreads();

        // O += P @ V
#pragma unroll 4
        for (int kk = 0; kk < 64; kk++) {
            float a[4], bb[4];
#pragma unroll
            for (int i = 0; i < 4; i++) a[i]  = Ps[(ty + 16 * i) * 64 + kk];
#pragma unroll
            for (int j = 0; j < 4; j++) bb[j] = Vs[kk * 64 + tx + 16 * j];
#pragma unroll
            for (int i = 0; i < 4; i++)
#pragma unroll
                for (int j = 0; j < 4; j++)
                    o[i][j] = fmaf(a[i], bb[j], o[i][j]);
        }
    }

    // Epilogue: out[b, q, h*64 + d] = o / l
#pragma unroll
    for (int i = 0; i < 4; i++) {
        float invl = 1.0f / l_i[i];
        int q = q0 + ty + 16 * i;
#pragma unroll
        for (int j = 0; j < 4; j++) {
            out[(size_t)(b * S_LEN + q) * E_DIM + h * D_HEAD + tx + 16 * j] =
                o[i][j] * invl;
        }
    }
}

// ---------------------------------------------------------------------------
extern "C" void kernel_launch(void* const* d_in, const int* in_sizes, int n_in,
                              void* d_out, int out_size)
{
    const float* x  = (const float*)d_in[0];
    const float* Wq = (const float*)d_in[1];
    const float* Wk = (const float*)d_in[2];
    const float* Wv = (const float*)d_in[3];
    const float* g  = (const float*)d_in[4];
    float* out = (float*)d_out;

    // 1) QKV projections: grid (N/128, M/128, 3)
    dim3 ggrid(E_DIM / 128, M_TOT / 128, 3);
    qkv_gemm<<<ggrid, 256>>>(x, Wq, Wk, Wv);

    // 2) L2 norm per head (Q gets g folded in)
    {
        const int chunks = M_TOT * H_NUM;      // 65536
        dim3 ngrid(chunks / 8, 2);             // 8 warps per block
        norm_heads<<<ngrid, 256>>>(g);
    }

    // 3) Flash attention
    {
        size_t smem = (size_t)(64 * 64 + 64 * 65 + 64 * 64 + 64 * 64) * sizeof(float);
        static int attr_set = 0;
        cudaFuncSetAttribute(attn_kernel, cudaFuncAttributeMaxDynamicSharedMemorySize,
                             (int)smem);
        (void)attr_set;
        dim3 agrid(S_LEN / 64, H_NUM, B_NUM);
        attn_kernel<<<agrid, 256, smem>>>(out);
    }
}

// round 2
// speedup vs baseline: 2.6925x; 2.6925x over previous
#include <cuda_runtime.h>
#include <math.h>

#define S_LEN  2048
#define E_DIM  1024
#define H_NUM  16
#define D_HEAD 64
#define B_NUM  2
#define M_TOT  (B_NUM * S_LEN)   // 4096

// ---------------- device scratch ----------------
__device__ float g_Q[(size_t)M_TOT * E_DIM];
__device__ float g_K[(size_t)M_TOT * E_DIM];
__device__ float g_V[(size_t)M_TOT * E_DIM];
__device__ float g_X[(size_t)M_TOT * E_DIM];        // tf32-rounded x
__device__ float g_Wq[(size_t)E_DIM * E_DIM];       // tf32-rounded weights
__device__ float g_Wk[(size_t)E_DIM * E_DIM];
__device__ float g_Wv[(size_t)E_DIM * E_DIM];

// ---------------- helpers ----------------
__device__ __forceinline__ unsigned f2tf(float f) {
    unsigned u;
    asm("cvt.rna.tf32.f32 %0, %1;" : "=r"(u) : "f"(f));
    return u;
}
__device__ __forceinline__ float f2tff(float f) { return __uint_as_float(f2tf(f)); }

__device__ __forceinline__ void mma_tf32(float c[4],
                                         unsigned a0, unsigned a1, unsigned a2, unsigned a3,
                                         unsigned b0, unsigned b1) {
    asm volatile(
        "mma.sync.aligned.m16n8k8.row.col.f32.tf32.tf32.f32 "
        "{%0,%1,%2,%3}, {%4,%5,%6,%7}, {%8,%9}, {%0,%1,%2,%3};"
        : "+f"(c[0]), "+f"(c[1]), "+f"(c[2]), "+f"(c[3])
        : "r"(a0), "r"(a1), "r"(a2), "r"(a3), "r"(b0), "r"(b1));
}

__device__ __forceinline__ void cp16(void* smem_dst, const void* gmem_src) {
    unsigned s = (unsigned)__cvta_generic_to_shared(smem_dst);
    asm volatile("cp.async.cg.shared.global [%0], [%1], 16;" :: "r"(s), "l"(gmem_src));
}
#define CP_COMMIT() asm volatile("cp.async.commit_group;")
#define CP_WAIT0()  asm volatile("cp.async.wait_group 0;")

// ---------------------------------------------------------------------------
// Kernel 0: elementwise tf32 rounding (so later kernels can cp.async raw)
// ---------------------------------------------------------------------------
__global__ void round_k(const float* __restrict__ src, float* __restrict__ dst, int n4)
{
    int i = blockIdx.x * blockDim.x + threadIdx.x;
    if (i >= n4) return;
    float4 v = ((const float4*)src)[i];
    v.x = f2tff(v.x); v.y = f2tff(v.y); v.z = f2tff(v.z); v.w = f2tff(v.w);
    ((float4*)dst)[i] = v;
}

// ---------------------------------------------------------------------------
// Kernel 1: C = x @ W^T  via m16n8k8 tf32 MMA. Tile 128x128, BK=32.
// 8 warps as 2(m) x 4(n): warp tile 64x32. cp.async double buffer.
// Smem stride 36 => fragment LDS addresses are (4r+k) mod 32: conflict-free.
// ---------------------------------------------------------------------------
#define AS_SZ (128 * 36)

__global__ __launch_bounds__(256, 2) void qkv_gemm()
{
    extern __shared__ float sm[];
    float* As[2] = { sm,            sm + AS_SZ };
    float* Bs[2] = { sm + 2*AS_SZ,  sm + 3*AS_SZ };

    const int z  = blockIdx.z;
    const float* W = (z == 0) ? g_Wq : (z == 1) ? g_Wk : g_Wv;
    float*       C = (z == 0) ? g_Q  : (z == 1) ? g_K  : g_V;

    const int m0   = blockIdx.y * 128;
    const int n0   = blockIdx.x * 128;
    const int t    = threadIdx.x;
    const int warp = t >> 5;
    const int lane = t & 31;
    const int wm   = warp >> 2;      // 0..1
    const int wn   = warp & 3;       // 0..3
    const int lr   = lane >> 2;      // 0..7
    const int lc   = lane & 3;       // 0..3

    float acc[4][4][4];
#pragma unroll
    for (int i = 0; i < 4; i++)
#pragma unroll
        for (int j = 0; j < 4; j++)
#pragma unroll
            for (int r = 0; r < 4; r++) acc[i][j][r] = 0.0f;

    auto prefetch = [&](int ks, int buf) {
        const int k0 = ks * 32;
#pragma unroll
        for (int i = 0; i < 4; i++) {
            int s   = t + i * 256;     // 0..1023
            int row = s >> 3;          // 0..127
            int c4  = s & 7;           // 0..7
            cp16(&As[buf][row * 36 + c4 * 4], &g_X[(size_t)(m0 + row) * E_DIM + k0 + c4 * 4]);
            cp16(&Bs[buf][row * 36 + c4 * 4], &W  [(size_t)(n0 + row) * E_DIM + k0 + c4 * 4]);
        }
    };

    prefetch(0, 0); CP_COMMIT();
    int buf = 0;

    for (int ks = 0; ks < 32; ks++) {
        CP_WAIT0();
        __syncthreads();
        if (ks + 1 < 32) { prefetch(ks + 1, buf ^ 1); CP_COMMIT(); }

#pragma unroll
        for (int kk = 0; kk < 4; kk++) {
            const int kb = kk * 8;
            unsigned af[4][4];
#pragma unroll
            for (int mi = 0; mi < 4; mi++) {
                int rb = wm * 64 + mi * 16 + lr;
                af[mi][0] = __float_as_uint(As[buf][rb       * 36 + kb + lc]);
                af[mi][1] = __float_as_uint(As[buf][(rb + 8) * 36 + kb + lc]);
                af[mi][2] = __float_as_uint(As[buf][rb       * 36 + kb + lc + 4]);
                af[mi][3] = __float_as_uint(As[buf][(rb + 8) * 36 + kb + lc + 4]);
            }
            unsigned bf[4][2];
#pragma unroll
            for (int ni = 0; ni < 4; ni++) {
                int nb = wn * 32 + ni * 8 + lr;
                bf[ni][0] = __float_as_uint(Bs[buf][nb * 36 + kb + lc]);
                bf[ni][1] = __float_as_uint(Bs[buf][nb * 36 + kb + lc + 4]);
            }
#pragma unroll
            for (int mi = 0; mi < 4; mi++)
#pragma unroll
                for (int ni = 0; ni < 4; ni++)
                    mma_tf32(acc[mi][ni], af[mi][0], af[mi][1], af[mi][2], af[mi][3],
                             bf[ni][0], bf[ni][1]);
        }
        buf ^= 1;
        __syncthreads();
    }

    // epilogue: C layout c0,c1 -> (row, 2lc), (row, 2lc+1); c2,c3 -> row+8
#pragma unroll
    for (int mi = 0; mi < 4; mi++) {
#pragma unroll
        for (int ni = 0; ni < 4; ni++) {
            int row = m0 + wm * 64 + mi * 16 + lr;
            int col = n0 + wn * 32 + ni * 8 + 2 * lc;
            float v0 = acc[mi][ni][0], v1 = acc[mi][ni][1];
            float v2 = acc[mi][ni][2], v3 = acc[mi][ni][3];
            if (z == 2) { v0 = f2tff(v0); v1 = f2tff(v1); v2 = f2tff(v2); v3 = f2tff(v3); }
            *(float2*)&C[(size_t)row * E_DIM + col]       = make_float2(v0, v1);
            *(float2*)&C[(size_t)(row + 8) * E_DIM + col] = make_float2(v2, v3);
        }
    }
}

// ---------------------------------------------------------------------------
// Kernel 2: per-head L2 norm; fold g into Q; write tf32-rounded values.
// ---------------------------------------------------------------------------
__global__ __launch_bounds__(256) void norm_heads(const float* __restrict__ gptr)
{
    int warp = (blockIdx.x * blockDim.x + threadIdx.x) >> 5;
    int lane = threadIdx.x & 31;
    const int total = M_TOT * H_NUM;
    if (warp >= total) return;

    float* buf = (blockIdx.y == 0) ? g_Q : g_K;
    float  sc  = (blockIdx.y == 0) ? *gptr : 1.0f;
    float* p   = buf + (size_t)warp * 64;

    float2 v = *(float2*)&p[lane * 2];
    float ss = v.x * v.x + v.y * v.y;
#pragma unroll
    for (int m = 16; m > 0; m >>= 1) ss += __shfl_xor_sync(0xffffffffu, ss, m);
    float inv = sc / fmaxf(sqrtf(ss), 1e-12f);
    v.x = f2tff(v.x * inv);
    v.y = f2tff(v.y * inv);
    *(float2*)&p[lane * 2] = v;
}

// ---------------------------------------------------------------------------
// Kernel 3: flash attention, tf32 MMA. Br=128, Bc=64, D=64.
// 8 warps, each owns 16 q-rows x all 64 cols => softmax is warp-local.
// |score| <= |g| (unit q,k; g folded into Q) => fixed max M0, no rescaling.
// Smem strides: 68 (A-pattern: 4r+k distinct), 72 (V B-pattern: 8k+n distinct).
// ---------------------------------------------------------------------------
#define QS_SZ (128 * 68)
#define KS_SZ (64 * 68)
#define VS_SZ (64 * 72)
#define PS_SZ (128 * 68)

__global__ __launch_bounds__(256) void attn_kernel(float* __restrict__ out,
                                                   const float* __restrict__ gptr)
{
    extern __shared__ float sm[];
    float* Qs    = sm;
    float* Ks[2] = { Qs + QS_SZ,        Qs + QS_SZ + KS_SZ };
    float* Vs[2] = { Ks[1] + KS_SZ,     Ks[1] + KS_SZ + VS_SZ };
    float* Ps    = Vs[1] + VS_SZ;

    const int b    = blockIdx.z;
    const int h    = blockIdx.y;
    const int q0   = blockIdx.x * 128;
    const int t    = threadIdx.x;
    const int warp = t >> 5;
    const int lane = t & 31;
    const int lr   = lane >> 2;   // 0..7
    const int lc   = lane & 3;    // 0..3
    const int w16  = warp * 16;

    const float M0 = fabsf(gptr[0]);

    const float* Qg = g_Q + ((size_t)b * S_LEN + q0) * E_DIM + h * D_HEAD;
    const float* Kg = g_K + (size_t)b * S_LEN * E_DIM + h * D_HEAD;
    const float* Vg = g_V + (size_t)b * S_LEN * E_DIM + h * D_HEAD;

    // load Q tile 128x64
#pragma unroll
    for (int i = 0; i < 8; i++) {
        int s  = t + i * 256;
        int r  = s >> 4;
        int c4 = s & 15;
        float4 v = *(const float4*)&Qg[(size_t)r * E_DIM + c4 * 4];
        *(float4*)&Qs[r * 68 + c4 * 4] = v;
    }

    auto prefetch = [&](int kt, int bufi) {
#pragma unroll
        for (int i = 0; i < 4; i++) {
            int s  = t + i * 256;
            int r  = s >> 4;
            int c4 = s & 15;
            cp16(&Ks[bufi][r * 68 + c4 * 4], &Kg[(size_t)(kt * 64 + r) * E_DIM + c4 * 4]);
            cp16(&Vs[bufi][r * 72 + c4 * 4], &Vg[(size_t)(kt * 64 + r) * E_DIM + c4 * 4]);
        }
    };

    prefetch(0, 0); CP_COMMIT();

    float oc[8][4];
#pragma unroll
    for (int ni = 0; ni < 8; ni++)
#pragma unroll
        for (int r = 0; r < 4; r++) oc[ni][r] = 0.0f;
    float l0 = 0.0f, l1 = 0.0f;

    int buf = 0;
    for (int kt = 0; kt < S_LEN / 64; kt++) {
        CP_WAIT0();
        __syncthreads();
        if (kt + 1 < S_LEN / 64) { prefetch(kt + 1, buf ^ 1); CP_COMMIT(); }

        // ---- S = Q K^T  (warp rows w16..w16+15, cols 0..63) ----
        float sv[8][4];
#pragma unroll
        for (int ni = 0; ni < 8; ni++)
#pragma unroll
            for (int r = 0; r < 4; r++) sv[ni][r] = 0.0f;

#pragma unroll
        for (int kk = 0; kk < 8; kk++) {
            const int kb = kk * 8;
            int rb = w16 + lr;
            unsigned a0 = __float_as_uint(Qs[rb       * 68 + kb + lc]);
            unsigned a1 = __float_as_uint(Qs[(rb + 8) * 68 + kb + lc]);
            unsigned a2 = __float_as_uint(Qs[rb       * 68 + kb + lc + 4]);
            unsigned a3 = __float_as_uint(Qs[(rb + 8) * 68 + kb + lc + 4]);
#pragma unroll
            for (int ni = 0; ni < 8; ni++) {
                int nb = ni * 8 + lr;
                unsigned b0 = __float_as_uint(Ks[buf][nb * 68 + kb + lc]);
                unsigned b1 = __float_as_uint(Ks[buf][nb * 68 + kb + lc + 4]);
                mma_tf32(sv[ni], a0, a1, a2, a3, b0, b1);
            }
        }

        // ---- P = exp(S - M0); accumulate row sums; stage P in smem ----
        __syncwarp();
#pragma unroll
        for (int ni = 0; ni < 8; ni++) {
            float p00 = __expf(sv[ni][0] - M0);
            float p01 = __expf(sv[ni][1] - M0);
            float p10 = __expf(sv[ni][2] - M0);
            float p11 = __expf(sv[ni][3] - M0);
            l0 += p00 + p01;
            l1 += p10 + p11;
            int col = ni * 8 + 2 * lc;
            *(float2*)&Ps[(w16 + lr)     * 68 + col] = make_float2(f2tff(p00), f2tff(p01));
            *(float2*)&Ps[(w16 + lr + 8) * 68 + col] = make_float2(f2tff(p10), f2tff(p11));
        }
        __syncwarp();

        // ---- O += P @ V ----
#pragma unroll
        for (int kk = 0; kk < 8; kk++) {
            const int kb = kk * 8;
            int rb = w16 + lr;
            unsigned a0 = __float_as_uint(Ps[rb       * 68 + kb + lc]);
            unsigned a1 = __float_as_uint(Ps[(rb + 8) * 68 + kb + lc]);
            unsigned a2 = __float_as_uint(Ps[rb       * 68 + kb + lc + 4]);
            unsigned a3 = __float_as_uint(Ps[(rb + 8) * 68 + kb + lc + 4]);
#pragma unroll
            for (int ni = 0; ni < 8; ni++) {
                unsigned b0 = __float_as_uint(Vs[buf][(kb + lc)     * 72 + ni * 8 + lr]);
                unsigned b1 = __float_as_uint(Vs[buf][(kb + lc + 4) * 72 + ni * 8 + lr]);
                mma_tf32(oc[ni], a0, a1, a2, a3, b0, b1);
            }
        }

        buf ^= 1;
        __syncthreads();
    }

    // ---- epilogue: normalize by row sums ----
    l0 += __shfl_xor_sync(0xffffffffu, l0, 1);
    l0 += __shfl_xor_sync(0xffffffffu, l0, 2);
    l1 += __shfl_xor_sync(0xffffffffu, l1, 1);
    l1 += __shfl_xor_sync(0xffffffffu, l1, 2);
    float inv0 = 1.0f / l0;
    float inv1 = 1.0f / l1;

    int ra = q0 + w16 + lr;
#pragma unroll
    for (int ni = 0; ni < 8; ni++) {
        int col = h * D_HEAD + ni * 8 + 2 * lc;
        *(float2*)&out[((size_t)b * S_LEN + ra) * E_DIM + col] =
            make_float2(oc[ni][0] * inv0, oc[ni][1] * inv0);
        *(float2*)&out[((size_t)b * S_LEN + ra + 8) * E_DIM + col] =
            make_float2(oc[ni][2] * inv1, oc[ni][3] * inv1);
    }
}

// ---------------------------------------------------------------------------
extern "C" void kernel_launch(void* const* d_in, const int* in_sizes, int n_in,
                              void* d_out, int out_size)
{
    const float* x  = (const float*)d_in[0];
    const float* Wq = (const float*)d_in[1];
    const float* Wk = (const float*)d_in[2];
    const float* Wv = (const float*)d_in[3];
    const float* g  = (const float*)d_in[4];
    float* out = (float*)d_out;

    float* gX;  cudaGetSymbolAddress((void**)&gX,  g_X);
    float* gWq; cudaGetSymbolAddress((void**)&gWq, g_Wq);
    float* gWk; cudaGetSymbolAddress((void**)&gWk, g_Wk);
    float* gWv; cudaGetSymbolAddress((void**)&gWv, g_Wv);

    // 0) tf32-round inputs so GEMMs can cp.async raw bytes
    round_k<<<(M_TOT * E_DIM / 4 + 255) / 256, 256>>>(x,  gX,  M_TOT * E_DIM / 4);
    round_k<<<(E_DIM * E_DIM / 4 + 255) / 256, 256>>>(Wq, gWq, E_DIM * E_DIM / 4);
    round_k<<<(E_DIM * E_DIM / 4 + 255) / 256, 256>>>(Wk, gWk, E_DIM * E_DIM / 4);
    round_k<<<(E_DIM * E_DIM / 4 + 255) / 256, 256>>>(Wv, gWv, E_DIM * E_DIM / 4);

    // 1) QKV projections (tf32 tensor core)
    {
        size_t smem = (size_t)4 * AS_SZ * sizeof(float);   // 73728
        cudaFuncSetAttribute(qkv_gemm, cudaFuncAttributeMaxDynamicSharedMemorySize,
                             (int)smem);
        dim3 grid(E_DIM / 128, M_TOT / 128, 3);
        qkv_gemm<<<grid, 256, smem>>>();
    }

    // 2) L2 norm per head (g folded into Q; outputs tf32-rounded)
    {
        const int chunks = M_TOT * H_NUM;
        dim3 ngrid(chunks / 8, 2);
        norm_heads<<<ngrid, 256>>>(g);
    }

    // 3) Flash attention (tf32 tensor core)
    {
        size_t smem = (size_t)(QS_SZ + 2 * KS_SZ + 2 * VS_SZ + PS_SZ) * sizeof(float);
        cudaFuncSetAttribute(attn_kernel, cudaFuncAttributeMaxDynamicSharedMemorySize,
                             (int)smem);
        dim3 agrid(S_LEN / 128, H_NUM, B_NUM);
        attn_kernel<<<agrid, 256, smem>>>(out, g);
    }
}

// round 3
// speedup vs baseline: 3.0414x; 1.1296x over previous
#include <cuda_runtime.h>
#include <math.h>

#define S_LEN  2048
#define E_DIM  1024
#define H_NUM  16
#define D_HEAD 64
#define B_NUM  2
#define M_TOT  (B_NUM * S_LEN)   // 4096

// ---------------- device scratch ----------------
__device__ float g_Q[(size_t)M_TOT * E_DIM];
__device__ float g_K[(size_t)M_TOT * E_DIM];
__device__ float g_V[(size_t)M_TOT * E_DIM];

// ---------------- helpers ----------------
__device__ __forceinline__ unsigned f2tf(float f) {
    unsigned u;
    asm("cvt.rna.tf32.f32 %0, %1;" : "=r"(u) : "f"(f));
    return u;
}
__device__ __forceinline__ float f2tff(float f) { return __uint_as_float(f2tf(f)); }

__device__ __forceinline__ void mma_tf32(float c[4],
                                         unsigned a0, unsigned a1, unsigned a2, unsigned a3,
                                         unsigned b0, unsigned b1) {
    asm volatile(
        "mma.sync.aligned.m16n8k8.row.col.f32.tf32.tf32.f32 "
        "{%0,%1,%2,%3}, {%4,%5,%6,%7}, {%8,%9}, {%0,%1,%2,%3};"
        : "+f"(c[0]), "+f"(c[1]), "+f"(c[2]), "+f"(c[3])
        : "r"(a0), "r"(a1), "r"(a2), "r"(a3), "r"(b0), "r"(b1));
}

__device__ __forceinline__ void cp16(void* smem_dst, const void* gmem_src) {
    unsigned s = (unsigned)__cvta_generic_to_shared(smem_dst);
    asm volatile("cp.async.cg.shared.global [%0], [%1], 16;" :: "r"(s), "l"(gmem_src));
}
#define CP_COMMIT() asm volatile("cp.async.commit_group;")
#define CP_WAIT0()  asm volatile("cp.async.wait_group 0;")

// ---------------------------------------------------------------------------
// Kernel 1: C = x @ W^T via m16n8k8 tf32 MMA. Tile 128x128, BK=32.
// Reads raw fp32 x/W; fragments rounded to tf32 in-register (cvt.rna).
// Smem stride 36 => fragment LDS addresses are (4r+k) mod 32: conflict-free.
// ---------------------------------------------------------------------------
#define AS_SZ (128 * 36)

__global__ __launch_bounds__(256, 2) void qkv_gemm(
    const float* __restrict__ x,
    const float* __restrict__ Wq,
    const float* __restrict__ Wk,
    const float* __restrict__ Wv)
{
    extern __shared__ float sm[];
    float* As[2] = { sm,            sm + AS_SZ };
    float* Bs[2] = { sm + 2*AS_SZ,  sm + 3*AS_SZ };

    const int z  = blockIdx.z;
    const float* W = (z == 0) ? Wq : (z == 1) ? Wk : Wv;
    float*       C = (z == 0) ? g_Q : (z == 1) ? g_K : g_V;

    const int m0   = blockIdx.y * 128;
    const int n0   = blockIdx.x * 128;
    const int t    = threadIdx.x;
    const int warp = t >> 5;
    const int lane = t & 31;
    const int wm   = warp >> 2;      // 0..1
    const int wn   = warp & 3;       // 0..3
    const int lr   = lane >> 2;      // 0..7
    const int lc   = lane & 3;       // 0..3

    float acc[4][4][4];
#pragma unroll
    for (int i = 0; i < 4; i++)
#pragma unroll
        for (int j = 0; j < 4; j++)
#pragma unroll
            for (int r = 0; r < 4; r++) acc[i][j][r] = 0.0f;

    auto prefetch = [&](int ks, int buf) {
        const int k0 = ks * 32;
#pragma unroll
        for (int i = 0; i < 4; i++) {
            int s   = t + i * 256;     // 0..1023
            int row = s >> 3;          // 0..127
            int c4  = s & 7;           // 0..7
            cp16(&As[buf][row * 36 + c4 * 4], &x[(size_t)(m0 + row) * E_DIM + k0 + c4 * 4]);
            cp16(&Bs[buf][row * 36 + c4 * 4], &W[(size_t)(n0 + row) * E_DIM + k0 + c4 * 4]);
        }
    };

    prefetch(0, 0); CP_COMMIT();
    int buf = 0;

    for (int ks = 0; ks < 32; ks++) {
        CP_WAIT0();
        __syncthreads();
        if (ks + 1 < 32) { prefetch(ks + 1, buf ^ 1); CP_COMMIT(); }

#pragma unroll
        for (int kk = 0; kk < 4; kk++) {
            const int kb = kk * 8;
            unsigned af[4][4];
#pragma unroll
            for (int mi = 0; mi < 4; mi++) {
                int rb = wm * 64 + mi * 16 + lr;
                af[mi][0] = f2tf(As[buf][rb       * 36 + kb + lc]);
                af[mi][1] = f2tf(As[buf][(rb + 8) * 36 + kb + lc]);
                af[mi][2] = f2tf(As[buf][rb       * 36 + kb + lc + 4]);
                af[mi][3] = f2tf(As[buf][(rb + 8) * 36 + kb + lc + 4]);
            }
            unsigned bf[4][2];
#pragma unroll
            for (int ni = 0; ni < 4; ni++) {
                int nb = wn * 32 + ni * 8 + lr;
                bf[ni][0] = f2tf(Bs[buf][nb * 36 + kb + lc]);
                bf[ni][1] = f2tf(Bs[buf][nb * 36 + kb + lc + 4]);
            }
#pragma unroll
            for (int mi = 0; mi < 4; mi++)
#pragma unroll
                for (int ni = 0; ni < 4; ni++)
                    mma_tf32(acc[mi][ni], af[mi][0], af[mi][1], af[mi][2], af[mi][3],
                             bf[ni][0], bf[ni][1]);
        }
        buf ^= 1;
        __syncthreads();
    }

#pragma unroll
    for (int mi = 0; mi < 4; mi++) {
#pragma unroll
        for (int ni = 0; ni < 4; ni++) {
            int row = m0 + wm * 64 + mi * 16 + lr;
            int col = n0 + wn * 32 + ni * 8 + 2 * lc;
            float v0 = acc[mi][ni][0], v1 = acc[mi][ni][1];
            float v2 = acc[mi][ni][2], v3 = acc[mi][ni][3];
            if (z == 2) { v0 = f2tff(v0); v1 = f2tff(v1); v2 = f2tff(v2); v3 = f2tff(v3); }
            *(float2*)&C[(size_t)row * E_DIM + col]       = make_float2(v0, v1);
            *(float2*)&C[(size_t)(row + 8) * E_DIM + col] = make_float2(v2, v3);
        }
    }
}

// ---------------------------------------------------------------------------
// Kernel 2: per-head L2 norm; fold g into Q; write tf32-rounded values.
// ---------------------------------------------------------------------------
__global__ __launch_bounds__(256) void norm_heads(const float* __restrict__ gptr)
{
    int warp = (blockIdx.x * blockDim.x + threadIdx.x) >> 5;
    int lane = threadIdx.x & 31;
    const int total = M_TOT * H_NUM;
    if (warp >= total) return;

    float* buf = (blockIdx.y == 0) ? g_Q : g_K;
    float  sc  = (blockIdx.y == 0) ? *gptr : 1.0f;
    float* p   = buf + (size_t)warp * 64;

    float2 v = *(float2*)&p[lane * 2];
    float ss = v.x * v.x + v.y * v.y;
#pragma unroll
    for (int m = 16; m > 0; m >>= 1) ss += __shfl_xor_sync(0xffffffffu, ss, m);
    float inv = sc / fmaxf(sqrtf(ss), 1e-12f);
    v.x = f2tff(v.x * inv);
    v.y = f2tff(v.y * inv);
    *(float2*)&p[lane * 2] = v;
}

// ---------------------------------------------------------------------------
// Kernel 3: flash attention, tf32 MMA. Br=128, Bc=64, D=64.
// Q fragments cached in registers (reused across all 32 k-tiles); the P
// staging buffer ALIASES the Q smem tile => smem 106.5KB => 2 CTAs/SM.
// |score| <= |g| (unit q,k; g folded into Q) => fixed max M0, no rescaling.
// ---------------------------------------------------------------------------
#define QS_SZ (128 * 68)
#define KS_SZ (64 * 68)
#define VS_SZ (64 * 72)

__global__ __launch_bounds__(256, 2) void attn_kernel(float* __restrict__ out,
                                                      const float* __restrict__ gptr)
{
    extern __shared__ float sm[];
    float* Qs    = sm;                 // 128*68, reused as Ps after Q->regs
    float* Ps    = sm;
    float* Ks[2] = { Qs + QS_SZ,        Qs + QS_SZ + KS_SZ };
    float* Vs[2] = { Ks[1] + KS_SZ,     Ks[1] + KS_SZ + VS_SZ };

    const int b    = blockIdx.z;
    const int h    = blockIdx.y;
    const int q0   = blockIdx.x * 128;
    const int t    = threadIdx.x;
    const int warp = t >> 5;
    const int lane = t & 31;
    const int lr   = lane >> 2;   // 0..7
    const int lc   = lane & 3;    // 0..3
    const int w16  = warp * 16;

    const float M0 = fabsf(gptr[0]);

    const float* Qg = g_Q + ((size_t)b * S_LEN + q0) * E_DIM + h * D_HEAD;
    const float* Kg = g_K + (size_t)b * S_LEN * E_DIM + h * D_HEAD;
    const float* Vg = g_V + (size_t)b * S_LEN * E_DIM + h * D_HEAD;

    auto prefetch = [&](int kt, int bufi) {
#pragma unroll
        for (int i = 0; i < 4; i++) {
            int s  = t + i * 256;
            int r  = s >> 4;
            int c4 = s & 15;
            cp16(&Ks[bufi][r * 68 + c4 * 4], &Kg[(size_t)(kt * 64 + r) * E_DIM + c4 * 4]);
            cp16(&Vs[bufi][r * 72 + c4 * 4], &Vg[(size_t)(kt * 64 + r) * E_DIM + c4 * 4]);
        }
    };
    prefetch(0, 0); CP_COMMIT();

    // stage Q tile once, pull fragments into registers
#pragma unroll
    for (int i = 0; i < 8; i++) {
        int s  = t + i * 256;
        int r  = s >> 4;
        int c4 = s & 15;
        float4 v = *(const float4*)&Qg[(size_t)r * E_DIM + c4 * 4];
        *(float4*)&Qs[r * 68 + c4 * 4] = v;
    }
    __syncthreads();

    unsigned qf[8][4];
#pragma unroll
    for (int kk = 0; kk < 8; kk++) {
        const int kb = kk * 8;
        int rb = w16 + lr;
        qf[kk][0] = __float_as_uint(Qs[rb       * 68 + kb + lc]);
        qf[kk][1] = __float_as_uint(Qs[(rb + 8) * 68 + kb + lc]);
        qf[kk][2] = __float_as_uint(Qs[rb       * 68 + kb + lc + 4]);
        qf[kk][3] = __float_as_uint(Qs[(rb + 8) * 68 + kb + lc + 4]);
    }
    // NOTE: Ps rows [w16, w16+16) are written/read only by this warp, and Q
    // fragments were read by this warp above => aliasing Qs is safe.

    float oc[8][4];
#pragma unroll
    for (int ni = 0; ni < 8; ni++)
#pragma unroll
        for (int r = 0; r < 4; r++) oc[ni][r] = 0.0f;
    float l0 = 0.0f, l1 = 0.0f;

    int buf = 0;
    for (int kt = 0; kt < S_LEN / 64; kt++) {
        CP_WAIT0();
        __syncthreads();
        if (kt + 1 < S_LEN / 64) { prefetch(kt + 1, buf ^ 1); CP_COMMIT(); }

        // ---- S = Q K^T ----
        float sv[8][4];
#pragma unroll
        for (int ni = 0; ni < 8; ni++)
#pragma unroll
            for (int r = 0; r < 4; r++) sv[ni][r] = 0.0f;

#pragma unroll
        for (int kk = 0; kk < 8; kk++) {
            const int kb = kk * 8;
#pragma unroll
            for (int ni = 0; ni < 8; ni++) {
                int nb = ni * 8 + lr;
                unsigned b0 = __float_as_uint(Ks[buf][nb * 68 + kb + lc]);
                unsigned b1 = __float_as_uint(Ks[buf][nb * 68 + kb + lc + 4]);
                mma_tf32(sv[ni], qf[kk][0], qf[kk][1], qf[kk][2], qf[kk][3], b0, b1);
            }
        }

        // ---- P = exp(S - M0); accumulate row sums; stage P in smem ----
        __syncwarp();
#pragma unroll
        for (int ni = 0; ni < 8; ni++) {
            float p00 = __expf(sv[ni][0] - M0);
            float p01 = __expf(sv[ni][1] - M0);
            float p10 = __expf(sv[ni][2] - M0);
            float p11 = __expf(sv[ni][3] - M0);
            l0 += p00 + p01;
            l1 += p10 + p11;
            int col = ni * 8 + 2 * lc;
            *(float2*)&Ps[(w16 + lr)     * 68 + col] = make_float2(f2tff(p00), f2tff(p01));
            *(float2*)&Ps[(w16 + lr + 8) * 68 + col] = make_float2(f2tff(p10), f2tff(p11));
        }
        __syncwarp();

        // ---- O += P @ V ----
#pragma unroll
        for (int kk = 0; kk < 8; kk++) {
            const int kb = kk * 8;
            int rb = w16 + lr;
            unsigned a0 = __float_as_uint(Ps[rb       * 68 + kb + lc]);
            unsigned a1 = __float_as_uint(Ps[(rb + 8) * 68 + kb + lc]);
            unsigned a2 = __float_as_uint(Ps[rb       * 68 + kb + lc + 4]);
            unsigned a3 = __float_as_uint(Ps[(rb + 8) * 68 + kb + lc + 4]);
#pragma unroll
            for (int ni = 0; ni < 8; ni++) {
                unsigned b0 = __float_as_uint(Vs[buf][(kb + lc)     * 72 + ni * 8 + lr]);
                unsigned b1 = __float_as_uint(Vs[buf][(kb + lc + 4) * 72 + ni * 8 + lr]);
                mma_tf32(oc[ni], a0, a1, a2, a3, b0, b1);
            }
        }

        buf ^= 1;
        __syncthreads();
    }

    // ---- epilogue ----
    l0 += __shfl_xor_sync(0xffffffffu, l0, 1);
    l0 += __shfl_xor_sync(0xffffffffu, l0, 2);
    l1 += __shfl_xor_sync(0xffffffffu, l1, 1);
    l1 += __shfl_xor_sync(0xffffffffu, l1, 2);
    float inv0 = 1.0f / l0;
    float inv1 = 1.0f / l1;

    int ra = q0 + w16 + lr;
#pragma unroll
    for (int ni = 0; ni < 8; ni++) {
        int col = h * D_HEAD + ni * 8 + 2 * lc;
        *(float2*)&out[((size_t)b * S_LEN + ra) * E_DIM + col] =
            make_float2(oc[ni][0] * inv0, oc[ni][1] * inv0);
        *(float2*)&out[((size_t)b * S_LEN + ra + 8) * E_DIM + col] =
            make_float2(oc[ni][2] * inv1, oc[ni][3] * inv1);
    }
}

// ---------------------------------------------------------------------------
extern "C" void kernel_launch(void* const* d_in, const int* in_sizes, int n_in,
                              void* d_out, int out_size)
{
    const float* x  = (const float*)d_in[0];
    const float* Wq = (const float*)d_in[1];
    const float* Wk = (const float*)d_in[2];
    const float* Wv = (const float*)d_in[3];
    const float* g  = (const float*)d_in[4];
    float* out = (float*)d_out;

    // 1) QKV projections (tf32 tensor core; in-register tf32 rounding)
    {
        size_t smem = (size_t)4 * AS_SZ * sizeof(float);   // 73728
        cudaFuncSetAttribute(qkv_gemm, cudaFuncAttributeMaxDynamicSharedMemorySize,
                             (int)smem);
        dim3 grid(E_DIM / 128, M_TOT / 128, 3);
        qkv_gemm<<<grid, 256, smem>>>(x, Wq, Wk, Wv);
    }

    // 2) L2 norm per head (g folded into Q; outputs tf32-rounded)
    {
        const int chunks = M_TOT * H_NUM;
        dim3 ngrid(chunks / 8, 2);
        norm_heads<<<ngrid, 256>>>(g);
    }

    // 3) Flash attention (tf32 tensor core, 2 CTAs/SM)
    {
        size_t smem = (size_t)(QS_SZ + 2 * KS_SZ + 2 * VS_SZ) * sizeof(float); // 106496
        cudaFuncSetAttribute(attn_kernel, cudaFuncAttributeMaxDynamicSharedMemorySize,
                             (int)smem);
        dim3 agrid(S_LEN / 128, H_NUM, B_NUM);
        attn_kernel<<<agrid, 256, smem>>>(out, g);
    }
}